// round 9
// baseline (speedup 1.0000x reference)
#include <cuda_runtime.h>
#include <cuda_bf16.h>
#include <math.h>

// IoU3DLoss: diagonal-only 3D IoU + (-log) mean. O(m) work, m=4096.
//
// 32 blocks x 32 threads (1 warp/block), 4 consecutive rows/thread via 7
// aligned float4 loads per tensor.
//
// Reduction strategy (fully integer, deterministic):
//  - per-thread: sum converted to 2^-20 fixed point (u32), count u32
//  - per-warp:   two single-instruction REDUX.ADD (no shfl chain)
//  - cross-block: ONE relaxed 64-bit atomicAdd of a packed word:
//      bits[19:63) = fixed-point sum   (total < 2^36 in fx units << ok)
//      bits[ 6:19) = valid count       (<= 4096)
//      bits[ 0: 6) = arrival counter   (<= 32)
//    The block seeing arrival==NBLK-1 holds the grand total in old+pack,
//    writes the scalar (fp32 math, rel err ~6e-8), resets for next replay.

#define OFFSET_C 1e-6f
#define EPS_C    1e-6f

#define NBLK 32
#define NTHR 32

#define SUM_SHIFT 19
#define CNT_SHIFT 6
#define FIXED_SCALE 1048576.0f   // 2^20

__device__ unsigned long long g_accum = 0ull;

// One row's contribution. r = 7 floats pred row, s = 7 floats target row.
__device__ __forceinline__ void row_iou(const float* r, const float* s,
                                        float& lsum, int& cnt)
{
    float px = r[0], py = r[1], pz = r[2];
    float pw = r[3], pl = r[4], ph = r[5], pr = r[6];
    float tx = s[0], ty = s[1], tz = s[2];
    float tw = s[3], tl = s[4], th = s[5], tr = s[6];

    // Axis-aligned extents of rotated BEV rect: corners {±A±B}, max = |A|+|B|.
    float pc = __cosf(pr), ps = __sinf(pr);
    float tc = __cosf(tr), ts = __sinf(tr);

    float pex = fabsf((0.5f * pw) * pc) + fabsf((0.5f * pl) * ps);
    float pey = fabsf((0.5f * pw) * ps) + fabsf((0.5f * pl) * pc);
    float tex = fabsf((0.5f * tw) * tc) + fabsf((0.5f * tl) * ts);
    float tey = fabsf((0.5f * tw) * ts) + fabsf((0.5f * tl) * tc);

    // BEV overlap (+offset before clamp, per reference)
    float wx = fmaxf(fminf(px + pex, tx + tex) - fmaxf(px - pex, tx - tex) + OFFSET_C, 0.0f);
    float wy = fmaxf(fminf(py + pey, ty + tey) - fmaxf(py - pey, ty - tey) + OFFSET_C, 0.0f);

    // Height overlap: z is box top, interval [z-h, z]
    float oh = fmaxf(fminf(pz, tz) - fmaxf(pz - ph, tz - th), 0.0f);

    float o3    = wx * wy * oh;
    float pvol  = pw * pl * ph;
    float tvol  = tw * tl * th;
    float denom = fmaxf(pvol + tvol - o3, EPS_C);
    float iou3d = fminf(fmaxf(__fdividef(o3, denom), EPS_C), 1.0f);

    if ((pw > 0.0f) && (pl > 0.0f) && (ph > 0.0f)) {
        lsum += -__logf(iou3d);   // always >= 0 since iou3d <= 1
        cnt  += 1;
    }
}

__global__ __launch_bounds__(NTHR, 1)
void iou3d_loss_kernel(const float* __restrict__ pred,
                       const float* __restrict__ target,
                       float* __restrict__ out, int m)
{
    float lsum = 0.0f;
    int   lcnt = 0;

    const int tid     = blockIdx.x * NTHR + threadIdx.x;
    const int nthread = gridDim.x * NTHR;

    // 4-row chunks: 28 floats = 7 float4 (112-byte chunk, 16B-aligned).
    for (int base = tid * 4; base < m; base += nthread * 4) {
        if (base + 3 < m) {
            float pa[28], ta[28];
            const float4* pv = (const float4*)(pred   + base * 7);
            const float4* tv = (const float4*)(target + base * 7);
            #pragma unroll
            for (int q = 0; q < 7; q++) {
                ((float4*)pa)[q] = pv[q];
                ((float4*)ta)[q] = tv[q];
            }
            #pragma unroll
            for (int j = 0; j < 4; j++)
                row_iou(pa + 7 * j, ta + 7 * j, lsum, lcnt);
        } else {
            for (int i = base; i < m; i++)
                row_iou(pred + 7 * i, target + 7 * i, lsum, lcnt);
        }
    }

    // ---- warp reduction: two single REDUX.ADD instructions ----
    // Per-thread fixed point: lsum <= 4 * 13.816 -> fx <= 5.8e7;
    // warp total <= 1.86e9 < 2^31, no overflow.
    int fx   = (int)lrintf(lsum * FIXED_SCALE);
    int wfx  = __reduce_add_sync(0xFFFFFFFFu, fx);
    int wcnt = __reduce_add_sync(0xFFFFFFFFu, lcnt);

    if (threadIdx.x == 0) {
        unsigned long long pack = ((unsigned long long)(unsigned)wfx << SUM_SHIFT)
                                | ((unsigned long long)(unsigned)wcnt << CNT_SHIFT)
                                | 1ull;
        unsigned long long old = atomicAdd(&g_accum, pack);

        if ((old & 63ull) == (unsigned long long)(NBLK - 1)) {
            unsigned long long tot = old + pack;
            unsigned cnt = (unsigned)((tot >> CNT_SHIFT) & 0x1FFFull);
            // fp32 final math: total fx ~ 2^36, rel err ~6e-8 — fine.
            float ssum = (float)(tot >> SUM_SHIFT) * (1.0f / FIXED_SCALE);
            out[0] = (cnt > 0u) ? __fdividef(ssum, (float)cnt) : 0.0f;
            atomicExch(&g_accum, 0ull);   // reset for next graph replay
        }
    }
}

extern "C" void kernel_launch(void* const* d_in, const int* in_sizes, int n_in,
                              void* d_out, int out_size)
{
    const float* pred   = (const float*)d_in[0];
    const float* target = (const float*)d_in[1];
    float* out = (float*)d_out;
    int m = in_sizes[0] / 7;

    iou3d_loss_kernel<<<NBLK, NTHR>>>(pred, target, out, m);
}